// round 2
// baseline (speedup 1.0000x reference)
#include <cuda_runtime.h>
#include <cuda_bf16.h>

#define NJ 32
#define TPB 128

__global__ void __launch_bounds__(TPB)
fk32_kernel(const float* __restrict__ angles,
            const float* __restrict__ offs,
            float* __restrict__ out,
            int batch)
{
    int b = blockIdx.x * TPB + threadIdx.x;
    if (b >= batch) return;

    const float4* __restrict__ src = reinterpret_cast<const float4*>(angles) + (size_t)b * 72; // 288 floats
    float4* __restrict__ dst       = reinterpret_cast<float4*>(out)         + (size_t)b * 24; // 96 floats

    // H36M parent table (constexpr -> fully folded under unroll)
    const int par[NJ] = {-1,0,1,2,3,4,0,6,7,8,9,0,11,12,13,14,12,16,17,18,
                         19,20,19,22,12,24,25,26,27,28,27,30};

    // Full local FK state; all indices are compile-time constants after
    // unrolling, so ptxas keeps only the live subset (max ~2 cross-group
    // rotations) in registers.
    float R[NJ][9];
    float P[NJ][3];

    #pragma unroll
    for (int g = 0; g < 8; ++g) {
        // ---- load 4 joints' rotation matrices = 36 floats = 9 aligned float4
        float a[36];
        #pragma unroll
        for (int q = 0; q < 9; ++q) {
            float4 v = src[g * 9 + q];
            a[4*q+0] = v.x; a[4*q+1] = v.y; a[4*q+2] = v.z; a[4*q+3] = v.w;
        }

        // ---- FK for joints 4g .. 4g+3
        #pragma unroll
        for (int jj = 0; jj < 4; ++jj) {
            const int j = g * 4 + jj;
            const float* Aj = &a[jj * 9];
            if (j == 0) {
                #pragma unroll
                for (int t = 0; t < 9; ++t) R[0][t] = Aj[t];
                P[0][0] = 0.f; P[0][1] = 0.f; P[0][2] = 0.f;
            } else {
                const int p = par[j];
                // rot[j] = A[j] @ rot[p]
                #pragma unroll
                for (int i = 0; i < 3; ++i) {
                    #pragma unroll
                    for (int l = 0; l < 3; ++l) {
                        R[j][i*3+l] = fmaf(Aj[i*3+0], R[p][0*3+l],
                                      fmaf(Aj[i*3+1], R[p][1*3+l],
                                           Aj[i*3+2] * R[p][2*3+l]));
                    }
                }
                // pos[j] = offsets[j] (row) @ rot[p] + pos[p]
                const float o0 = __ldg(&offs[j*3+0]);
                const float o1 = __ldg(&offs[j*3+1]);
                const float o2 = __ldg(&offs[j*3+2]);
                #pragma unroll
                for (int l = 0; l < 3; ++l) {
                    P[j][l] = fmaf(o0, R[p][0*3+l],
                              fmaf(o1, R[p][1*3+l],
                              fmaf(o2, R[p][2*3+l], P[p][l])));
                }
            }
        }

        // ---- store 4 joints' positions = 12 floats = 3 aligned float4
        const int j0 = g * 4;
        float4 s0 = make_float4(P[j0+0][0], P[j0+0][1], P[j0+0][2], P[j0+1][0]);
        float4 s1 = make_float4(P[j0+1][1], P[j0+1][2], P[j0+2][0], P[j0+2][1]);
        float4 s2 = make_float4(P[j0+2][2], P[j0+3][0], P[j0+3][1], P[j0+3][2]);
        dst[g*3+0] = s0;
        dst[g*3+1] = s1;
        dst[g*3+2] = s2;
    }
}

extern "C" void kernel_launch(void* const* d_in, const int* in_sizes, int n_in,
                              void* d_out, int out_size)
{
    const float* angles = (const float*)d_in[0];
    const float* offs   = (const float*)d_in[1];
    float* out          = (float*)d_out;

    int batch = in_sizes[0] / (NJ * 9);   // 262144
    int blocks = (batch + TPB - 1) / TPB;

    fk32_kernel<<<blocks, TPB>>>(angles, offs, out, batch);
}